// round 1
// baseline (speedup 1.0000x reference)
#include <cuda_runtime.h>

// Local2d: out[b,o,h,w] = sum_{i,kk,ll} weight[o,h,w,i,kk,ll] * x[b,i,h-1+kk,w-1+ll] + bias[o,h,w]
// Shapes: x[64,64,32,32], weight[128,32,32,64,3,3], bias[128,32,32], out[64,128,32,32]
// One block per spatial location p = h*32+w: GEMM D[128(o) x 64(b)] = W[128 x 576] * P[576 x 64]

#define B_    64
#define CI_   64
#define CO_   128
#define KTOT  576
#define KC    64
#define NCHUNK 9           // 576 / 64
#define WPITCH 130         // floats per k-row of W tile (128 + 2 pad)
#define PPITCH 68          // floats per k-row of P tile (64 + 4 pad)
#define STAGE_FLOATS (KC*WPITCH + KC*PPITCH)   // 8320 + 4352 = 12672
#define SMEM_BYTES   (2 * STAGE_FLOATS * 4)    // 101376 bytes

typedef unsigned long long ull;

__device__ __forceinline__ ull pack2(float a, float b) {
    ull r;
    asm("mov.b64 %0, {%1, %2};" : "=l"(r) : "f"(a), "f"(b));
    return r;
}

// packed fp32x2 FMA (Blackwell): d = a*b + d, lanewise on the two f32 halves
__device__ __forceinline__ void ffma2(ull& d, ull a, ull b) {
    asm("fma.rn.f32x2 %0, %1, %2, %0;" : "+l"(d) : "l"(a), "l"(b));
}

extern "C" __global__ void __launch_bounds__(256, 2)
local2d_kernel(const float* __restrict__ x,
               const float* __restrict__ wgt,
               const float* __restrict__ bias,
               float* __restrict__ out)
{
    extern __shared__ float smem[];

    const int p   = blockIdx.x;          // spatial location 0..1023
    const int h   = p >> 5;
    const int w   = p & 31;
    const int tid = threadIdx.x;

    // compute-tile mapping: 16 (o-groups) x 16 (b-groups)
    const int to = tid & 15;             // o pairs at {2*to, 2*to+1} + 32*j, j<4
    const int tb = tid >> 4;             // b at {4*tb .. 4*tb+3}

    // W global-load mapping: float4 index g = tid + 256*jj -> o = (tid>>4)+16*jj, kq = tid&15
    const int kq   = tid & 15;
    const int orow = tid >> 4;

    // P global-load mapping: element e = tid + 256*jj -> kidx = tid&63, b = (tid>>6)+4*jj
    const int kidx = tid & 63;
    const int brow = tid >> 6;

    float* stage0 = smem;
    float* stage1 = smem + STAGE_FLOATS;

    float4 wreg[8];
    float  preg[16];

    ull acc[4][4];
    #pragma unroll
    for (int j = 0; j < 4; ++j)
        #pragma unroll
        for (int bb = 0; bb < 4; ++bb)
            acc[j][bb] = 0ull;

    // ---- chunk 0 loads ----
    {
        const int c = 0;
        #pragma unroll
        for (int jj = 0; jj < 8; ++jj) {
            int o = orow + 16 * jj;
            wreg[jj] = *reinterpret_cast<const float4*>(
                wgt + ((o << 10) + p) * KTOT + c * KC + (kq << 2));
        }
        int k  = c * KC + kidx;
        int i  = k / 9;
        int r  = k - i * 9;
        int kk = r / 3;
        int ll = r - kk * 3;
        int y  = h - 1 + kk;
        int xw = w - 1 + ll;
        bool valid = ((unsigned)y < 32u) && ((unsigned)xw < 32u);
        const float* basep = x + (i << 10) + (y << 5) + xw;
        #pragma unroll
        for (int jj = 0; jj < 16; ++jj) {
            int b = brow + 4 * jj;
            preg[jj] = valid ? basep[b << 16] : 0.0f;
        }
    }
    // ---- STS chunk 0 -> stage 0 ----
    {
        float* Wp = stage0;
        float* Pp = stage0 + KC * WPITCH;
        #pragma unroll
        for (int jj = 0; jj < 8; ++jj) {
            int o = orow + 16 * jj;
            const float* v = reinterpret_cast<const float*>(&wreg[jj]);
            #pragma unroll
            for (int t = 0; t < 4; ++t)
                Wp[((kq << 2) + t) * WPITCH + o] = v[t];
        }
        #pragma unroll
        for (int jj = 0; jj < 16; ++jj)
            Pp[kidx * PPITCH + brow + 4 * jj] = preg[jj];
    }
    __syncthreads();

    for (int c = 0; c < NCHUNK; ++c) {
        // prefetch next chunk into registers (latency hidden by compute below)
        if (c + 1 < NCHUNK) {
            const int cn = c + 1;
            #pragma unroll
            for (int jj = 0; jj < 8; ++jj) {
                int o = orow + 16 * jj;
                wreg[jj] = *reinterpret_cast<const float4*>(
                    wgt + ((o << 10) + p) * KTOT + cn * KC + (kq << 2));
            }
            int k  = cn * KC + kidx;
            int i  = k / 9;
            int r  = k - i * 9;
            int kk = r / 3;
            int ll = r - kk * 3;
            int y  = h - 1 + kk;
            int xw = w - 1 + ll;
            bool valid = ((unsigned)y < 32u) && ((unsigned)xw < 32u);
            const float* basep = x + (i << 10) + (y << 5) + xw;
            #pragma unroll
            for (int jj = 0; jj < 16; ++jj) {
                int b = brow + 4 * jj;
                preg[jj] = valid ? basep[b << 16] : 0.0f;
            }
        }

        // compute from current stage
        {
            const float* Wp = (c & 1) ? stage1 : stage0;
            const float* Pp = Wp + KC * WPITCH;
            #pragma unroll 8
            for (int k = 0; k < KC; ++k) {
                float4 pv = *reinterpret_cast<const float4*>(Pp + k * PPITCH + (tb << 2));
                ull pb0 = pack2(pv.x, pv.x);
                ull pb1 = pack2(pv.y, pv.y);
                ull pb2 = pack2(pv.z, pv.z);
                ull pb3 = pack2(pv.w, pv.w);
                #pragma unroll
                for (int j = 0; j < 4; ++j) {
                    ull w2 = *reinterpret_cast<const ull*>(Wp + k * WPITCH + 2 * to + 32 * j);
                    ffma2(acc[j][0], w2, pb0);
                    ffma2(acc[j][1], w2, pb1);
                    ffma2(acc[j][2], w2, pb2);
                    ffma2(acc[j][3], w2, pb3);
                }
            }
        }

        // store prefetched chunk into the other stage
        if (c + 1 < NCHUNK) {
            float* Wp = ((c + 1) & 1) ? stage1 : stage0;
            float* Pp = Wp + KC * WPITCH;
            #pragma unroll
            for (int jj = 0; jj < 8; ++jj) {
                int o = orow + 16 * jj;
                const float* v = reinterpret_cast<const float*>(&wreg[jj]);
                #pragma unroll
                for (int t = 0; t < 4; ++t)
                    Wp[((kq << 2) + t) * WPITCH + o] = v[t];
            }
            #pragma unroll
            for (int jj = 0; jj < 16; ++jj)
                Pp[kidx * PPITCH + brow + 4 * jj] = preg[jj];
            __syncthreads();
        }
    }

    // ---- epilogue: out[b, o, p] = acc + bias[o, p] ----
    #pragma unroll
    for (int j = 0; j < 4; ++j) {
        int o0 = 2 * to + 32 * j;
        float bv0 = bias[(o0 << 10) + p];
        float bv1 = bias[((o0 + 1) << 10) + p];
        #pragma unroll
        for (int bb = 0; bb < 4; ++bb) {
            int b = (tb << 2) + bb;
            ull v = acc[j][bb];
            float lo = __uint_as_float((unsigned)(v & 0xffffffffull));
            float hi = __uint_as_float((unsigned)(v >> 32));
            out[((b * CO_ + o0) << 10) + p]     = lo + bv0;
            out[((b * CO_ + o0 + 1) << 10) + p] = hi + bv1;
        }
    }
}

extern "C" void kernel_launch(void* const* d_in, const int* in_sizes, int n_in,
                              void* d_out, int out_size)
{
    const float* x    = (const float*)d_in[0];
    const float* wgt  = (const float*)d_in[1];
    const float* bias = (const float*)d_in[2];
    float* out        = (float*)d_out;

    cudaFuncSetAttribute(local2d_kernel,
                         cudaFuncAttributeMaxDynamicSharedMemorySize, SMEM_BYTES);
    local2d_kernel<<<1024, 256, SMEM_BYTES>>>(x, wgt, bias, out);
}

// round 7
// speedup vs baseline: 1.7023x; 1.7023x over previous
#include <cuda_runtime.h>
#include <cstdint>

// Local2d via classic mma.sync TF32 (sm_80+ PTX, no 'a'-target features needed):
//   per location p: D[o=128, b=64] = W_p[128 x 576] * P_p[576 x 64]  (+ bias)
// x[64,64,32,32], weight[128,32,32,64,3,3], bias[128,32,32], out[64,128,32,32]

#define KC      32
#define NCH     18                // 576 / 32
#define APITCH  36                // floats per row (KC + 4): conflict-free frag LDS
#define W_STAGE_F (128 * APITCH)  // 4608 floats
#define P_STAGE_F (64 * APITCH)   // 2304 floats
#define STAGE_F   (W_STAGE_F + P_STAGE_F)     // 6912 floats
#define SM_OFFS_B 0               // 576 ints
#define SM_STAGE_B 2560           // 16B aligned, after offsets
#define SMEM_TOTAL (SM_STAGE_B + 2 * STAGE_F * 4)   // 2560 + 55296 = 57856

__device__ __forceinline__ uint32_t fbits(float f) { return __float_as_uint(f); }

__device__ __forceinline__ void mma_tf32(float* c, const uint32_t* a, const uint32_t* b) {
    asm volatile(
        "mma.sync.aligned.m16n8k8.row.col.f32.tf32.tf32.f32 "
        "{%0,%1,%2,%3}, {%4,%5,%6,%7}, {%8,%9}, {%0,%1,%2,%3};"
        : "+f"(c[0]), "+f"(c[1]), "+f"(c[2]), "+f"(c[3])
        : "r"(a[0]), "r"(a[1]), "r"(a[2]), "r"(a[3]), "r"(b[0]), "r"(b[1]));
}

extern "C" __global__ void __launch_bounds__(256, 2)
local2d_mma(const float* __restrict__ x,
            const float* __restrict__ wgt,
            const float* __restrict__ bias,
            float* __restrict__ out)
{
    extern __shared__ char smem[];
    int*   offs   = reinterpret_cast<int*>(smem + SM_OFFS_B);
    float* stage0 = reinterpret_cast<float*>(smem + SM_STAGE_B);
    float* stage1 = stage0 + STAGE_F;

    const int p    = blockIdx.x;
    const int h    = p >> 5;
    const int w    = p & 31;
    const int tid  = threadIdx.x;
    const int wid  = tid >> 5;
    const int lane = tid & 31;
    const int qr   = lane >> 2;       // 0..7
    const int qc   = lane & 3;        // 0..3

    // warp tile: wo in 0..3 (o-tile of 32), wb in 0..1 (b-tile of 32)
    const int wo = wid & 3;
    const int wb = wid >> 2;
    const int o0w = wo * 32;
    const int n0w = wb * 32;

    // global-load mappings
    const int gor = tid >> 3;         // W: o row within group of 32 per j
    const int gkq = tid & 7;          // W/P: float4 index within KC
    const int gbr = tid >> 3;         // P: b row (0..31 per j)

    // build patch-offset table
    for (int k = tid; k < 576; k += 256) {
        int i  = k / 9;
        int r  = k - i * 9;
        int kk = r / 3;
        int ll = r - kk * 3;
        int y  = h - 1 + kk;
        int xw = w - 1 + ll;
        bool valid = ((unsigned)y < 32u) && ((unsigned)xw < 32u);
        offs[k] = valid ? ((i << 10) + (y << 5) + xw) : -1;
    }
    __syncthreads();

    float4 wr[4];
    float4 pr[2];

    // ---- load chunk cc into registers ----
    #define LOAD_CHUNK(cc) do {                                                    \
        _Pragma("unroll")                                                          \
        for (int j = 0; j < 4; ++j) {                                              \
            int o = gor + 32 * j;                                                  \
            wr[j] = *reinterpret_cast<const float4*>(                              \
                wgt + (o * 1024 + p) * 576 + (cc) * KC + gkq * 4);                 \
        }                                                                          \
        _Pragma("unroll")                                                          \
        for (int j = 0; j < 2; ++j) {                                              \
            int b = gbr + 32 * j;                                                  \
            int4 o4 = *reinterpret_cast<const int4*>(offs + (cc) * KC + gkq * 4);  \
            const float* xb = x + (b << 16);                                       \
            pr[j].x = (o4.x >= 0) ? xb[o4.x] : 0.0f;                               \
            pr[j].y = (o4.y >= 0) ? xb[o4.y] : 0.0f;                               \
            pr[j].z = (o4.z >= 0) ? xb[o4.z] : 0.0f;                               \
            pr[j].w = (o4.w >= 0) ? xb[o4.w] : 0.0f;                               \
        }                                                                          \
    } while (0)

    // ---- store registers into stage (W: [o][k] pitch 36, P: [b][k] pitch 36) ----
    #define STORE_CHUNK(sp) do {                                                   \
        float* Wb = (sp);                                                          \
        float* Pb = (sp) + W_STAGE_F;                                              \
        _Pragma("unroll")                                                          \
        for (int j = 0; j < 4; ++j) {                                              \
            int o = gor + 32 * j;                                                  \
            *reinterpret_cast<float4*>(Wb + o * APITCH + gkq * 4) = wr[j];         \
        }                                                                          \
        _Pragma("unroll")                                                          \
        for (int j = 0; j < 2; ++j) {                                              \
            int b = gbr + 32 * j;                                                  \
            *reinterpret_cast<float4*>(Pb + b * APITCH + gkq * 4) = pr[j];         \
        }                                                                          \
    } while (0)

    float acc[2][4][4];
    #pragma unroll
    for (int mt = 0; mt < 2; ++mt)
        #pragma unroll
        for (int nt = 0; nt < 4; ++nt)
            #pragma unroll
            for (int e = 0; e < 4; ++e)
                acc[mt][nt][e] = 0.0f;

    LOAD_CHUNK(0);
    STORE_CHUNK(stage0);
    __syncthreads();

    for (int c = 0; c < NCH; ++c) {
        if (c + 1 < NCH) LOAD_CHUNK(c + 1);   // LDGs in flight during compute

        const float* Ws = (c & 1) ? stage1 : stage0;
        const float* Ps = Ws + W_STAGE_F;

        #pragma unroll
        for (int ks = 0; ks < 4; ++ks) {
            const int kb = ks * 8;
            uint32_t afr[2][4], bfr[4][2];
            #pragma unroll
            for (int mt = 0; mt < 2; ++mt) {
                const float* Ab = Ws + (o0w + mt * 16 + qr) * APITCH + kb + qc;
                afr[mt][0] = fbits(Ab[0]);
                afr[mt][1] = fbits(Ab[8 * APITCH]);
                afr[mt][2] = fbits(Ab[4]);
                afr[mt][3] = fbits(Ab[8 * APITCH + 4]);
            }
            #pragma unroll
            for (int nt = 0; nt < 4; ++nt) {
                const float* Bb = Ps + (n0w + nt * 8 + qr) * APITCH + kb + qc;
                bfr[nt][0] = fbits(Bb[0]);
                bfr[nt][1] = fbits(Bb[4]);
            }
            #pragma unroll
            for (int mt = 0; mt < 2; ++mt)
                #pragma unroll
                for (int nt = 0; nt < 4; ++nt)
                    mma_tf32(acc[mt][nt], afr[mt], bfr[nt]);
        }

        if (c + 1 < NCH) {
            float* Wn = ((c + 1) & 1) ? stage1 : stage0;
            __syncthreads();                  // everyone done reading stage before overwrite
            STORE_CHUNK(Wn);
            __syncthreads();
        }
    }

    // ---- epilogue: out[b, o, p] = acc + bias[o, p] ----
    #pragma unroll
    for (int mt = 0; mt < 2; ++mt) {
        const int ob = o0w + mt * 16 + qr;
        const float bv0 = bias[(ob << 10) + p];
        const float bv1 = bias[((ob + 8) << 10) + p];
        #pragma unroll
        for (int nt = 0; nt < 4; ++nt) {
            const int bb = n0w + nt * 8 + 2 * qc;
            float* o00 = out + ((bb * 128 + ob) << 10) + p;
            o00[0]                 = acc[mt][nt][0] + bv0;     // (ob,   bb)
            o00[128 << 10]         = acc[mt][nt][1] + bv0;     // (ob,   bb+1)
            o00[8 << 10]           = acc[mt][nt][2] + bv1;     // (ob+8, bb)
            o00[(128 << 10) + (8 << 10)] = acc[mt][nt][3] + bv1; // (ob+8, bb+1)
        }
    }
}

extern "C" void kernel_launch(void* const* d_in, const int* in_sizes, int n_in,
                              void* d_out, int out_size)
{
    const float* x    = (const float*)d_in[0];
    const float* wgt  = (const float*)d_in[1];
    const float* bias = (const float*)d_in[2];
    float* out        = (float*)d_out;

    cudaFuncSetAttribute(local2d_mma,
                         cudaFuncAttributeMaxDynamicSharedMemorySize, SMEM_TOTAL);
    local2d_mma<<<1024, 256, SMEM_TOTAL>>>(x, wgt, bias, out);
}

// round 9
// speedup vs baseline: 2.4965x; 1.4666x over previous
#include <cuda_runtime.h>
#include <cstdint>

// Local2d via classic mma.sync TF32.
//   per location p: D[o=128, b=64] = W_p[128 x 576] * P_p[576 x 64]  (+ bias)
// x[64,64,32,32], weight[128,32,32,64,3,3], bias[128,32,32], out[64,128,32,32]
//
// Round 8: pre-transpose x -> x_t[c_in, h, w, b] (b fastest) so the P-tile
// ("patches") load is fully coalesced (64-float b-runs) instead of a b-major
// scatter that touched ~16 lines per LDG. P smem becomes [k][b] pitch 72
// (conflict-free B-frag reads: bank = 8*qc + qr).

#define KC      32
#define NCH     18                // 576 / 32
#define APITCH  36                // W smem: [o][k] pitch (KC+4), conflict-free A-frag LDS
#define PPITCH  72                // P smem: [k][b] pitch (64+8),  conflict-free B-frag LDS
#define W_STAGE_F (128 * APITCH)  // 4608 floats
#define P_STAGE_F (KC * PPITCH)   // 2304 floats
#define STAGE_F   (W_STAGE_F + P_STAGE_F)     // 6912 floats
#define SM_OFFS_B 0               // 576 ints
#define SM_STAGE_B 2560
#define SMEM_TOTAL (SM_STAGE_B + 2 * STAGE_F * 4)   // 57856 bytes

// x transposed: [c_in=64][h=32][w=32][b=64]
__device__ float g_xt[64 * 32 * 32 * 64];

__device__ __forceinline__ uint32_t fbits(float f) { return __float_as_uint(f); }

__device__ __forceinline__ void mma_tf32(float* c, const uint32_t* a, const uint32_t* b) {
    asm volatile(
        "mma.sync.aligned.m16n8k8.row.col.f32.tf32.tf32.f32 "
        "{%0,%1,%2,%3}, {%4,%5,%6,%7}, {%8,%9}, {%0,%1,%2,%3};"
        : "+f"(c[0]), "+f"(c[1]), "+f"(c[2]), "+f"(c[3])
        : "r"(a[0]), "r"(a[1]), "r"(a[2]), "r"(a[3]), "r"(b[0]), "r"(b[1]));
}

// ---- transpose kernel: x[b][i][y][xw] -> g_xt[i][y][xw][b] ----
extern "C" __global__ void __launch_bounds__(256)
xpose_kernel(const float* __restrict__ x)
{
    __shared__ float tile[64][33];
    const int iy = blockIdx.x;        // 0..2047 : (i, y)
    const int i  = iy >> 5;
    const int y  = iy & 31;
    const int tid = threadIdx.x;

    // read coalesced over xw
    {
        const int xw = tid & 31;
        const int b0 = tid >> 5;      // 0..7
        #pragma unroll
        for (int jj = 0; jj < 8; ++jj) {
            int b = b0 + 8 * jj;
            tile[b][xw] = x[(((b << 6) + i) << 10) + (y << 5) + xw];
        }
    }
    __syncthreads();

    // write coalesced over b
    {
        float* dst = g_xt + ((i << 10) + (y << 5)) * 64;
        #pragma unroll
        for (int jj = 0; jj < 8; ++jj) {
            int idx = tid + 256 * jj;
            int b   = idx & 63;
            int xw  = idx >> 6;
            dst[(xw << 6) + b] = tile[b][xw];
        }
    }
}

extern "C" __global__ void __launch_bounds__(256, 2)
local2d_mma(const float* __restrict__ wgt,
            const float* __restrict__ bias,
            float* __restrict__ out)
{
    extern __shared__ char smem[];
    int*   offs   = reinterpret_cast<int*>(smem + SM_OFFS_B);
    float* stage0 = reinterpret_cast<float*>(smem + SM_STAGE_B);
    float* stage1 = stage0 + STAGE_F;

    const int p    = blockIdx.x;
    const int h    = p >> 5;
    const int w    = p & 31;
    const int tid  = threadIdx.x;
    const int wid  = tid >> 5;
    const int lane = tid & 31;
    const int qr   = lane >> 2;       // 0..7
    const int qc   = lane & 3;        // 0..3

    // warp tile: 32(o) x 32(b), grid 4 x 2
    const int wo  = wid & 3;
    const int wb  = wid >> 2;
    const int o0w = wo * 32;
    const int n0w = wb * 32;

    // W global-load mapping
    const int gor = tid >> 3;         // o row (+32j)
    const int gkq = tid & 7;          // float4 index within KC

    // patch-offset table: base index into g_xt (in floats), -1 if padded tap
    for (int k = tid; k < 576; k += 256) {
        int i  = k / 9;
        int r  = k - i * 9;
        int kk = r / 3;
        int ll = r - kk * 3;
        int y  = h - 1 + kk;
        int xw = w - 1 + ll;
        bool valid = ((unsigned)y < 32u) && ((unsigned)xw < 32u);
        offs[k] = valid ? ((((i << 5) + y) << 5) + xw) << 6 : -1;
    }
    __syncthreads();

    float4 wr[4];
    float4 pr[2];

    // ---- load chunk cc into registers ----
    // W: coalesced float4, 4 per thread.
    // P: from g_xt, slot = tid + 256*j -> k_local = slot>>4 (0..31), bq = slot&15;
    //    16 consecutive lanes read 256B contiguous b-run.
    #define LOAD_CHUNK(cc) do {                                                    \
        _Pragma("unroll")                                                          \
        for (int j = 0; j < 4; ++j) {                                              \
            int o = gor + 32 * j;                                                  \
            wr[j] = *reinterpret_cast<const float4*>(                              \
                wgt + (o * 1024 + p) * 576 + (cc) * KC + gkq * 4);                 \
        }                                                                          \
        _Pragma("unroll")                                                          \
        for (int j = 0; j < 2; ++j) {                                              \
            int slot = tid + 256 * j;                                              \
            int kl   = slot >> 4;                                                  \
            int bq   = slot & 15;                                                  \
            int base = offs[(cc) * KC + kl];                                       \
            if (base >= 0)                                                         \
                pr[j] = *reinterpret_cast<const float4*>(g_xt + base + bq * 4);    \
            else                                                                   \
                pr[j] = make_float4(0.f, 0.f, 0.f, 0.f);                           \
        }                                                                          \
    } while (0)

    // ---- store regs into stage: W [o][k] pitch 36, P [k][b] pitch 72 ----
    #define STORE_CHUNK(sp) do {                                                   \
        float* Wb = (sp);                                                          \
        float* Pb = (sp) + W_STAGE_F;                                              \
        _Pragma("unroll")                                                          \
        for (int j = 0; j < 4; ++j) {                                              \
            int o = gor + 32 * j;                                                  \
            *reinterpret_cast<float4*>(Wb + o * APITCH + gkq * 4) = wr[j];         \
        }                                                                          \
        _Pragma("unroll")                                                          \
        for (int j = 0; j < 2; ++j) {                                              \
            int slot = tid + 256 * j;                                              \
            int kl   = slot >> 4;                                                  \
            int bq   = slot & 15;                                                  \
            *reinterpret_cast<float4*>(Pb + kl * PPITCH + bq * 4) = pr[j];         \
        }                                                                          \
    } while (0)

    float acc[2][4][4];
    #pragma unroll
    for (int mt = 0; mt < 2; ++mt)
        #pragma unroll
        for (int nt = 0; nt < 4; ++nt)
            #pragma unroll
            for (int e = 0; e < 4; ++e)
                acc[mt][nt][e] = 0.0f;

    LOAD_CHUNK(0);
    STORE_CHUNK(stage0);
    __syncthreads();

    for (int c = 0; c < NCH; ++c) {
        if (c + 1 < NCH) LOAD_CHUNK(c + 1);   // LDGs in flight during compute

        const float* Ws = (c & 1) ? stage1 : stage0;
        const float* Ps = Ws + W_STAGE_F;

        #pragma unroll
        for (int ks = 0; ks < 4; ++ks) {
            const int kb = ks * 8;
            uint32_t afr[2][4], bfr[4][2];
            #pragma unroll
            for (int mt = 0; mt < 2; ++mt) {
                const float* Ab = Ws + (o0w + mt * 16 + qr) * APITCH + kb + qc;
                afr[mt][0] = fbits(Ab[0]);
                afr[mt][1] = fbits(Ab[8 * APITCH]);
                afr[mt][2] = fbits(Ab[4]);
                afr[mt][3] = fbits(Ab[8 * APITCH + 4]);
            }
            #pragma unroll
            for (int nt = 0; nt < 4; ++nt) {
                const float* Bb = Ps + (kb + qc) * PPITCH + n0w + nt * 8 + qr;
                bfr[nt][0] = fbits(Bb[0]);
                bfr[nt][1] = fbits(Bb[4 * PPITCH]);
            }
            #pragma unroll
            for (int mt = 0; mt < 2; ++mt)
                #pragma unroll
                for (int nt = 0; nt < 4; ++nt)
                    mma_tf32(acc[mt][nt], afr[mt], bfr[nt]);
        }

        if (c + 1 < NCH) {
            float* Wn = ((c + 1) & 1) ? stage1 : stage0;
            __syncthreads();                  // all reads of old stage done
            STORE_CHUNK(Wn);
            __syncthreads();
        }
    }

    // ---- epilogue: out[b, o, p] = acc + bias[o, p] ----
    #pragma unroll
    for (int mt = 0; mt < 2; ++mt) {
        const int ob = o0w + mt * 16 + qr;
        const float bv0 = bias[(ob << 10) + p];
        const float bv1 = bias[((ob + 8) << 10) + p];
        #pragma unroll
        for (int nt = 0; nt < 4; ++nt) {
            const int bb = n0w + nt * 8 + 2 * qc;
            float* o00 = out + ((bb * 128 + ob) << 10) + p;
            o00[0]                       = acc[mt][nt][0] + bv0;  // (ob,   bb)
            o00[128 << 10]               = acc[mt][nt][1] + bv0;  // (ob,   bb+1)
            o00[8 << 10]                 = acc[mt][nt][2] + bv1;  // (ob+8, bb)
            o00[(128 << 10) + (8 << 10)] = acc[mt][nt][3] + bv1;  // (ob+8, bb+1)
        }
    }
}

extern "C" void kernel_launch(void* const* d_in, const int* in_sizes, int n_in,
                              void* d_out, int out_size)
{
    const float* x    = (const float*)d_in[0];
    const float* wgt  = (const float*)d_in[1];
    const float* bias = (const float*)d_in[2];
    float* out        = (float*)d_out;

    xpose_kernel<<<2048, 256>>>(x);

    cudaFuncSetAttribute(local2d_mma,
                         cudaFuncAttributeMaxDynamicSharedMemorySize, SMEM_TOTAL);
    local2d_mma<<<1024, 256, SMEM_TOTAL>>>(wgt, bias, out);
}

// round 12
// speedup vs baseline: 3.2694x; 1.3096x over previous
#include <cuda_runtime.h>
#include <cstdint>

// Local2d via classic mma.sync TF32.
//   per location p: D[o=128, b=64] = W_p[128 x 576] * P_p[576 x 64]  (+ bias)
// x[64,64,32,32], weight[128,32,32,64,3,3], bias[128,32,32], out[64,128,32,32]
//
// R8: pre-transpose x -> g_xt[c,h,w,b] (b fastest) -> coalesced P loads.
// R10: stage output as g_ot[p][o][b] (contiguous 32KB per location, float2
//      stores) and transpose back to out[b][o][p] (+bias) in a third kernel.

#define KC      32
#define NCH     18                // 576 / 32
#define APITCH  36                // W smem: [o][k] pitch (KC+4)
#define PPITCH  72                // P smem: [k][b] pitch (64+8)
#define W_STAGE_F (128 * APITCH)  // 4608 floats
#define P_STAGE_F (KC * PPITCH)   // 2304 floats
#define STAGE_F   (W_STAGE_F + P_STAGE_F)     // 6912 floats
#define SM_OFFS_B 0               // 576 ints
#define SM_STAGE_B 2560
#define SMEM_TOTAL (SM_STAGE_B + 2 * STAGE_F * 4)   // 57856 bytes

__device__ float g_xt[64 * 32 * 32 * 64];   // [c][h][w][b]
__device__ float g_ot[1024 * 128 * 64];     // [p][o][b]

__device__ __forceinline__ uint32_t fbits(float f) { return __float_as_uint(f); }

__device__ __forceinline__ void mma_tf32(float* c, const uint32_t* a, const uint32_t* b) {
    asm volatile(
        "mma.sync.aligned.m16n8k8.row.col.f32.tf32.tf32.f32 "
        "{%0,%1,%2,%3}, {%4,%5,%6,%7}, {%8,%9}, {%0,%1,%2,%3};"
        : "+f"(c[0]), "+f"(c[1]), "+f"(c[2]), "+f"(c[3])
        : "r"(a[0]), "r"(a[1]), "r"(a[2]), "r"(a[3]), "r"(b[0]), "r"(b[1]));
}

// ---- x[b][i][y][xw] -> g_xt[i][y][xw][b] ----
extern "C" __global__ void __launch_bounds__(256)
xpose_kernel(const float* __restrict__ x)
{
    __shared__ float tile[64][33];
    const int iy = blockIdx.x;        // (i, y)
    const int i  = iy >> 5;
    const int y  = iy & 31;
    const int tid = threadIdx.x;

    {
        const int xw = tid & 31;
        const int b0 = tid >> 5;
        #pragma unroll
        for (int jj = 0; jj < 8; ++jj) {
            int b = b0 + 8 * jj;
            tile[b][xw] = x[(((b << 6) + i) << 10) + (y << 5) + xw];
        }
    }
    __syncthreads();
    {
        float* dst = g_xt + ((i << 10) + (y << 5)) * 64;
        #pragma unroll
        for (int jj = 0; jj < 8; ++jj) {
            int idx = tid + 256 * jj;
            int b   = idx & 63;
            int xw  = idx >> 6;
            dst[(xw << 6) + b] = tile[b][xw];
        }
    }
}

// ---- g_ot[p][o][b] -> out[b][o][p], + bias[o][p] ----
// grid: (o, p-tile of 32) = 128 x 32, 256 threads
extern "C" __global__ void __launch_bounds__(256)
opose_kernel(const float* __restrict__ bias, float* __restrict__ out)
{
    __shared__ float tile[32][65];
    __shared__ float bss[32];
    const int o   = blockIdx.x;
    const int p0  = blockIdx.y << 5;
    const int tid = threadIdx.x;

    if (tid < 32) bss[tid] = bias[(o << 10) + p0 + tid];

    // read: coalesced over b (64 contiguous floats per (p,o) row)
    {
        const int b  = tid & 63;
        const int pl0 = tid >> 6;     // 0..3
        #pragma unroll
        for (int jj = 0; jj < 8; ++jj) {
            int pl = pl0 + 4 * jj;
            tile[pl][b] = g_ot[(size_t)(p0 + pl) * 8192 + (o << 6) + b];
        }
    }
    __syncthreads();

    // write: coalesced over p (32 contiguous floats per (b,o) row)
    {
        const int pl = tid & 31;
        const int b0 = tid >> 5;      // 0..7
        #pragma unroll
        for (int jj = 0; jj < 8; ++jj) {
            int b = b0 + 8 * jj;
            out[(((b << 7) + o) << 10) + p0 + pl] = tile[pl][b] + bss[pl];
        }
    }
}

extern "C" __global__ void __launch_bounds__(256, 2)
local2d_mma(const float* __restrict__ wgt)
{
    extern __shared__ char smem[];
    int*   offs   = reinterpret_cast<int*>(smem + SM_OFFS_B);
    float* stage0 = reinterpret_cast<float*>(smem + SM_STAGE_B);
    float* stage1 = stage0 + STAGE_F;

    const int p    = blockIdx.x;
    const int h    = p >> 5;
    const int w    = p & 31;
    const int tid  = threadIdx.x;
    const int wid  = tid >> 5;
    const int lane = tid & 31;
    const int qr   = lane >> 2;
    const int qc   = lane & 3;

    const int wo  = wid & 3;
    const int wb  = wid >> 2;
    const int o0w = wo * 32;
    const int n0w = wb * 32;

    const int gor = tid >> 3;
    const int gkq = tid & 7;

    for (int k = tid; k < 576; k += 256) {
        int i  = k / 9;
        int r  = k - i * 9;
        int kk = r / 3;
        int ll = r - kk * 3;
        int y  = h - 1 + kk;
        int xw = w - 1 + ll;
        bool valid = ((unsigned)y < 32u) && ((unsigned)xw < 32u);
        offs[k] = valid ? ((((i << 5) + y) << 5) + xw) << 6 : -1;
    }
    __syncthreads();

    float4 wr[4];
    float4 pr[2];

    #define LOAD_CHUNK(cc) do {                                                    \
        _Pragma("unroll")                                                          \
        for (int j = 0; j < 4; ++j) {                                              \
            int o = gor + 32 * j;                                                  \
            wr[j] = *reinterpret_cast<const float4*>(                              \
                wgt + (o * 1024 + p) * 576 + (cc) * KC + gkq * 4);                 \
        }                                                                          \
        _Pragma("unroll")                                                          \
        for (int j = 0; j < 2; ++j) {                                              \
            int slot = tid + 256 * j;                                              \
            int kl   = slot >> 4;                                                  \
            int bq   = slot & 15;                                                  \
            int base = offs[(cc) * KC + kl];                                       \
            if (base >= 0)                                                         \
                pr[j] = *reinterpret_cast<const float4*>(g_xt + base + bq * 4);    \
            else                                                                   \
                pr[j] = make_float4(0.f, 0.f, 0.f, 0.f);                           \
        }                                                                          \
    } while (0)

    #define STORE_CHUNK(sp) do {                                                   \
        float* Wb = (sp);                                                          \
        float* Pb = (sp) + W_STAGE_F;                                              \
        _Pragma("unroll")                                                          \
        for (int j = 0; j < 4; ++j) {                                              \
            int o = gor + 32 * j;                                                  \
            *reinterpret_cast<float4*>(Wb + o * APITCH + gkq * 4) = wr[j];         \
        }                                                                          \
        _Pragma("unroll")                                                          \
        for (int j = 0; j < 2; ++j) {                                              \
            int slot = tid + 256 * j;                                              \
            int kl   = slot >> 4;                                                  \
            int bq   = slot & 15;                                                  \
            *reinterpret_cast<float4*>(Pb + kl * PPITCH + bq * 4) = pr[j];         \
        }                                                                          \
    } while (0)

    float acc[2][4][4];
    #pragma unroll
    for (int mt = 0; mt < 2; ++mt)
        #pragma unroll
        for (int nt = 0; nt < 4; ++nt)
            #pragma unroll
            for (int e = 0; e < 4; ++e)
                acc[mt][nt][e] = 0.0f;

    LOAD_CHUNK(0);
    STORE_CHUNK(stage0);
    __syncthreads();

    for (int c = 0; c < NCH; ++c) {
        if (c + 1 < NCH) LOAD_CHUNK(c + 1);

        const float* Ws = (c & 1) ? stage1 : stage0;
        const float* Ps = Ws + W_STAGE_F;

        #pragma unroll
        for (int ks = 0; ks < 4; ++ks) {
            const int kb = ks * 8;
            uint32_t afr[2][4], bfr[4][2];
            #pragma unroll
            for (int mt = 0; mt < 2; ++mt) {
                const float* Ab = Ws + (o0w + mt * 16 + qr) * APITCH + kb + qc;
                afr[mt][0] = fbits(Ab[0]);
                afr[mt][1] = fbits(Ab[8 * APITCH]);
                afr[mt][2] = fbits(Ab[4]);
                afr[mt][3] = fbits(Ab[8 * APITCH + 4]);
            }
            #pragma unroll
            for (int nt = 0; nt < 4; ++nt) {
                const float* Bb = Ps + (kb + qc) * PPITCH + n0w + nt * 8 + qr;
                bfr[nt][0] = fbits(Bb[0]);
                bfr[nt][1] = fbits(Bb[4 * PPITCH]);
            }
            #pragma unroll
            for (int mt = 0; mt < 2; ++mt)
                #pragma unroll
                for (int nt = 0; nt < 4; ++nt)
                    mma_tf32(acc[mt][nt], afr[mt], bfr[nt]);
        }

        if (c + 1 < NCH) {
            float* Wn = ((c + 1) & 1) ? stage1 : stage0;
            __syncthreads();
            STORE_CHUNK(Wn);
            __syncthreads();
        }
    }

    // ---- epilogue: g_ot[p][o][b] = acc  (contiguous 32KB block per p) ----
    {
        float* op = g_ot + (size_t)p * 8192;
        #pragma unroll
        for (int mt = 0; mt < 2; ++mt) {
            const int ob = o0w + mt * 16 + qr;
            #pragma unroll
            for (int nt = 0; nt < 4; ++nt) {
                const int bb = n0w + nt * 8 + 2 * qc;
                *reinterpret_cast<float2*>(op + (ob << 6) + bb) =
                    make_float2(acc[mt][nt][0], acc[mt][nt][1]);
                *reinterpret_cast<float2*>(op + ((ob + 8) << 6) + bb) =
                    make_float2(acc[mt][nt][2], acc[mt][nt][3]);
            }
        }
    }
}

extern "C" void kernel_launch(void* const* d_in, const int* in_sizes, int n_in,
                              void* d_out, int out_size)
{
    const float* x    = (const float*)d_in[0];
    const float* wgt  = (const float*)d_in[1];
    const float* bias = (const float*)d_in[2];
    float* out        = (float*)d_out;

    xpose_kernel<<<2048, 256>>>(x);

    cudaFuncSetAttribute(local2d_mma,
                         cudaFuncAttributeMaxDynamicSharedMemorySize, SMEM_TOTAL);
    local2d_mma<<<1024, 256, SMEM_TOTAL>>>(wgt);

    opose_kernel<<<dim3(128, 32), 256>>>(bias, out);
}

// round 13
// speedup vs baseline: 3.3150x; 1.0140x over previous
#include <cuda_runtime.h>
#include <cstdint>

// Local2d via classic mma.sync TF32.
//   per location p: D[o=128, b=64] = W_p[128 x 576] * P_p[576 x 64]  (+ bias)
// R8:  x -> g_xt[c,h,w,b] pre-transpose (coalesced P loads)
// R10: out staged as g_ot[p][o][b], transposed back (+bias) in 3rd kernel
// R13: 512 threads / 16 warps per CTA (warp tile 32o x 16b) -> 32 warps/SM,
//      hides LDS->MMA latency that capped issue at 16%.

#define KC      32
#define NCH     18
#define APITCH  36                // W smem [o][k] pitch
#define PPITCH  72                // P smem [k][b] pitch
#define W_STAGE_F (128 * APITCH)  // 4608 floats
#define P_STAGE_F (KC * PPITCH)   // 2304 floats
#define STAGE_F   (W_STAGE_F + P_STAGE_F)
#define SM_OFFS_B 0
#define SM_STAGE_B 2560
#define SMEM_TOTAL (SM_STAGE_B + 2 * STAGE_F * 4)   // 57856 bytes

__device__ float g_xt[64 * 32 * 32 * 64];   // [c][h][w][b]
__device__ float g_ot[1024 * 128 * 64];     // [p][o][b]

__device__ __forceinline__ uint32_t fbits(float f) { return __float_as_uint(f); }

__device__ __forceinline__ void mma_tf32(float* c, const uint32_t* a, const uint32_t* b) {
    asm volatile(
        "mma.sync.aligned.m16n8k8.row.col.f32.tf32.tf32.f32 "
        "{%0,%1,%2,%3}, {%4,%5,%6,%7}, {%8,%9}, {%0,%1,%2,%3};"
        : "+f"(c[0]), "+f"(c[1]), "+f"(c[2]), "+f"(c[3])
        : "r"(a[0]), "r"(a[1]), "r"(a[2]), "r"(a[3]), "r"(b[0]), "r"(b[1]));
}

// ---- x[b][i][y][xw] -> g_xt[i][y][xw][b] ----
extern "C" __global__ void __launch_bounds__(256)
xpose_kernel(const float* __restrict__ x)
{
    __shared__ float tile[64][33];
    const int iy = blockIdx.x;
    const int i  = iy >> 5;
    const int y  = iy & 31;
    const int tid = threadIdx.x;

    {
        const int xw = tid & 31;
        const int b0 = tid >> 5;
        #pragma unroll
        for (int jj = 0; jj < 8; ++jj) {
            int b = b0 + 8 * jj;
            tile[b][xw] = x[(((b << 6) + i) << 10) + (y << 5) + xw];
        }
    }
    __syncthreads();
    {
        float* dst = g_xt + ((i << 10) + (y << 5)) * 64;
        #pragma unroll
        for (int jj = 0; jj < 8; ++jj) {
            int idx = tid + 256 * jj;
            int b   = idx & 63;
            int xw  = idx >> 6;
            dst[(xw << 6) + b] = tile[b][xw];
        }
    }
}

// ---- g_ot[p][o][b] -> out[b][o][p], + bias[o][p] ----
extern "C" __global__ void __launch_bounds__(256)
opose_kernel(const float* __restrict__ bias, float* __restrict__ out)
{
    __shared__ float tile[32][65];
    __shared__ float bss[32];
    const int o   = blockIdx.x;
    const int p0  = blockIdx.y << 5;
    const int tid = threadIdx.x;

    if (tid < 32) bss[tid] = bias[(o << 10) + p0 + tid];

    {
        const int b   = tid & 63;
        const int pl0 = tid >> 6;
        #pragma unroll
        for (int jj = 0; jj < 8; ++jj) {
            int pl = pl0 + 4 * jj;
            tile[pl][b] = g_ot[(size_t)(p0 + pl) * 8192 + (o << 6) + b];
        }
    }
    __syncthreads();
    {
        const int pl = tid & 31;
        const int b0 = tid >> 5;
        #pragma unroll
        for (int jj = 0; jj < 8; ++jj) {
            int b = b0 + 8 * jj;
            out[(((b << 7) + o) << 10) + p0 + pl] = tile[pl][b] + bss[pl];
        }
    }
}

extern "C" __global__ void __launch_bounds__(512, 2)
local2d_mma(const float* __restrict__ wgt)
{
    extern __shared__ char smem[];
    int*   offs   = reinterpret_cast<int*>(smem + SM_OFFS_B);
    float* stage0 = reinterpret_cast<float*>(smem + SM_STAGE_B);
    float* stage1 = stage0 + STAGE_F;

    const int p    = blockIdx.x;
    const int h    = p >> 5;
    const int w    = p & 31;
    const int tid  = threadIdx.x;
    const int wid  = tid >> 5;
    const int lane = tid & 31;
    const int qr   = lane >> 2;
    const int qc   = lane & 3;

    // 16 warps: 4(o) x 4(b) grid of 32x16 warp tiles
    const int wo  = wid & 3;
    const int wb  = wid >> 2;
    const int o0w = wo * 32;
    const int n0w = wb * 16;

    // global-load mappings (512 threads)
    const int gor = tid >> 3;         // W: o row (j adds 64)
    const int gkq = tid & 7;          // W: float4 within KC
    const int pkl = tid >> 4;         // P: k row 0..31
    const int pbq = tid & 15;         // P: float4 within b

    for (int k = tid; k < 576; k += 512) {
        int i  = k / 9;
        int r  = k - i * 9;
        int kk = r / 3;
        int ll = r - kk * 3;
        int y  = h - 1 + kk;
        int xw = w - 1 + ll;
        bool valid = ((unsigned)y < 32u) && ((unsigned)xw < 32u);
        offs[k] = valid ? ((((i << 5) + y) << 5) + xw) << 6 : -1;
    }
    __syncthreads();

    float4 wr[2];
    float4 pr;

    #define LOAD_CHUNK(cc) do {                                                    \
        _Pragma("unroll")                                                          \
        for (int j = 0; j < 2; ++j) {                                              \
            int o = gor + 64 * j;                                                  \
            wr[j] = *reinterpret_cast<const float4*>(                              \
                wgt + (o * 1024 + p) * 576 + (cc) * KC + gkq * 4);                 \
        }                                                                          \
        {                                                                          \
            int base = offs[(cc) * KC + pkl];                                      \
            if (base >= 0)                                                         \
                pr = *reinterpret_cast<const float4*>(g_xt + base + pbq * 4);      \
            else                                                                   \
                pr = make_float4(0.f, 0.f, 0.f, 0.f);                              \
        }                                                                          \
    } while (0)

    #define STORE_CHUNK(sp) do {                                                   \
        float* Wb = (sp);                                                          \
        float* Pb = (sp) + W_STAGE_F;                                              \
        _Pragma("unroll")                                                          \
        for (int j = 0; j < 2; ++j) {                                              \
            int o = gor + 64 * j;                                                  \
            *reinterpret_cast<float4*>(Wb + o * APITCH + gkq * 4) = wr[j];         \
        }                                                                          \
        *reinterpret_cast<float4*>(Pb + pkl * PPITCH + pbq * 4) = pr;              \
    } while (0)

    float acc[2][2][4];
    #pragma unroll
    for (int mt = 0; mt < 2; ++mt)
        #pragma unroll
        for (int nt = 0; nt < 2; ++nt)
            #pragma unroll
            for (int e = 0; e < 4; ++e)
                acc[mt][nt][e] = 0.0f;

    LOAD_CHUNK(0);
    STORE_CHUNK(stage0);
    __syncthreads();

    for (int c = 0; c < NCH; ++c) {
        if (c + 1 < NCH) LOAD_CHUNK(c + 1);

        const float* Ws = (c & 1) ? stage1 : stage0;
        const float* Ps = Ws + W_STAGE_F;

        #pragma unroll
        for (int ks = 0; ks < 4; ++ks) {
            const int kb = ks * 8;
            uint32_t afr[2][4], bfr[2][2];
            #pragma unroll
            for (int mt = 0; mt < 2; ++mt) {
                const float* Ab = Ws + (o0w + mt * 16 + qr) * APITCH + kb + qc;
                afr[mt][0] = fbits(Ab[0]);
                afr[mt][1] = fbits(Ab[8 * APITCH]);
                afr[mt][2] = fbits(Ab[4]);
                afr[mt][3] = fbits(Ab[8 * APITCH + 4]);
            }
            #pragma unroll
            for (int nt = 0; nt < 2; ++nt) {
                const float* Bb = Ps + (kb + qc) * PPITCH + n0w + nt * 8 + qr;
                bfr[nt][0] = fbits(Bb[0]);
                bfr[nt][1] = fbits(Bb[4 * PPITCH]);
            }
            #pragma unroll
            for (int mt = 0; mt < 2; ++mt)
                #pragma unroll
                for (int nt = 0; nt < 2; ++nt)
                    mma_tf32(acc[mt][nt], afr[mt], bfr[nt]);
        }

        if (c + 1 < NCH) {
            float* Wn = ((c + 1) & 1) ? stage1 : stage0;
            __syncthreads();
            STORE_CHUNK(Wn);
            __syncthreads();
        }
    }

    // ---- epilogue: g_ot[p][o][b] = acc ----
    {
        float* op = g_ot + (size_t)p * 8192;
        #pragma unroll
        for (int mt = 0; mt < 2; ++mt) {
            const int ob = o0w + mt * 16 + qr;
            #pragma unroll
            for (int nt = 0; nt < 2; ++nt) {
                const int bb = n0w + nt * 8 + 2 * qc;
                *reinterpret_cast<float2*>(op + (ob << 6) + bb) =
                    make_float2(acc[mt][nt][0], acc[mt][nt][1]);
                *reinterpret_cast<float2*>(op + ((ob + 8) << 6) + bb) =
                    make_float2(acc[mt][nt][2], acc[mt][nt][3]);
            }
        }
    }
}

extern "C" void kernel_launch(void* const* d_in, const int* in_sizes, int n_in,
                              void* d_out, int out_size)
{
    const float* x    = (const float*)d_in[0];
    const float* wgt  = (const float*)d_in[1];
    const float* bias = (const float*)d_in[2];
    float* out        = (float*)d_out;

    xpose_kernel<<<2048, 256>>>(x);

    cudaFuncSetAttribute(local2d_mma,
                         cudaFuncAttributeMaxDynamicSharedMemorySize, SMEM_TOTAL);
    local2d_mma<<<1024, 512, SMEM_TOTAL>>>(wgt);

    opose_kernel<<<dim3(128, 32), 256>>>(bias, out);
}

// round 16
// speedup vs baseline: 3.7818x; 1.1408x over previous
#include <cuda_runtime.h>
#include <cstdint>

// Local2d via classic mma.sync TF32.
//   per location p: D[o=128, b=64] = W_p[128 x 576] * P_p[576 x 64]  (+ bias)
// R8:  x -> g_xt[c,h,w,b] pre-transpose (coalesced P loads)
// R10: out staged as g_ot[p][o][b], transposed back (+bias) in 3rd kernel
// R14: back to 8-warp 32x32 warp tiles (bytes-optimal) + cp.async feeding
//      smem directly (no LDG->reg->STS staging) -> fits 3 CTAs/SM (24 warps).

#define KC      32
#define NCH     18
#define APITCH  36                // W smem [o][k] pitch: bank = 4*qr+qc, conflict-free
#define PPITCH  72                // P smem [k][b] pitch: bank = 8*qc+qr, conflict-free
#define W_STAGE_F (128 * APITCH)  // 4608 floats
#define P_STAGE_F (KC * PPITCH)   // 2304 floats
#define STAGE_F   (W_STAGE_F + P_STAGE_F)
#define SM_OFFS_B 0
#define SM_STAGE_B 2560
#define SMEM_TOTAL (SM_STAGE_B + 2 * STAGE_F * 4)   // 57856 bytes -> 3 CTAs/SM

__device__ float g_xt[64 * 32 * 32 * 64];   // [c][h][w][b]
__device__ float g_ot[1024 * 128 * 64];     // [p][o][b]

__device__ __forceinline__ uint32_t fbits(float f) { return __float_as_uint(f); }

__device__ __forceinline__ void mma_tf32(float* c, const uint32_t* a, const uint32_t* b) {
    asm volatile(
        "mma.sync.aligned.m16n8k8.row.col.f32.tf32.tf32.f32 "
        "{%0,%1,%2,%3}, {%4,%5,%6,%7}, {%8,%9}, {%0,%1,%2,%3};"
        : "+f"(c[0]), "+f"(c[1]), "+f"(c[2]), "+f"(c[3])
        : "r"(a[0]), "r"(a[1]), "r"(a[2]), "r"(a[3]), "r"(b[0]), "r"(b[1]));
}

__device__ __forceinline__ uint32_t smem_u32(const void* p) {
    uint32_t a;
    asm("{ .reg .u64 t; cvta.to.shared.u64 t, %1; cvt.u32.u64 %0, t; }" : "=r"(a) : "l"(p));
    return a;
}
__device__ __forceinline__ void cp16(uint32_t dst, const void* src, int srcbytes) {
    asm volatile("cp.async.ca.shared.global [%0], [%1], 16, %2;"
                 :: "r"(dst), "l"(src), "r"(srcbytes) : "memory");
}
#define CP_COMMIT() asm volatile("cp.async.commit_group;" ::: "memory")
#define CP_WAIT(n)  asm volatile("cp.async.wait_group %0;" :: "n"(n) : "memory")

// ---- x[b][i][y][xw] -> g_xt[i][y][xw][b] ----
extern "C" __global__ void __launch_bounds__(256)
xpose_kernel(const float* __restrict__ x)
{
    __shared__ float tile[64][33];
    const int iy = blockIdx.x;
    const int i  = iy >> 5;
    const int y  = iy & 31;
    const int tid = threadIdx.x;

    {
        const int xw = tid & 31;
        const int b0 = tid >> 5;
        #pragma unroll
        for (int jj = 0; jj < 8; ++jj) {
            int b = b0 + 8 * jj;
            tile[b][xw] = x[(((b << 6) + i) << 10) + (y << 5) + xw];
        }
    }
    __syncthreads();
    {
        float* dst = g_xt + ((i << 10) + (y << 5)) * 64;
        #pragma unroll
        for (int jj = 0; jj < 8; ++jj) {
            int idx = tid + 256 * jj;
            int b   = idx & 63;
            int xw  = idx >> 6;
            dst[(xw << 6) + b] = tile[b][xw];
        }
    }
}

// ---- g_ot[p][o][b] -> out[b][o][p], + bias[o][p] ----
extern "C" __global__ void __launch_bounds__(256)
opose_kernel(const float* __restrict__ bias, float* __restrict__ out)
{
    __shared__ float tile[32][65];
    __shared__ float bss[32];
    const int o   = blockIdx.x;
    const int p0  = blockIdx.y << 5;
    const int tid = threadIdx.x;

    if (tid < 32) bss[tid] = bias[(o << 10) + p0 + tid];

    {
        const int b   = tid & 63;
        const int pl0 = tid >> 6;
        #pragma unroll
        for (int jj = 0; jj < 8; ++jj) {
            int pl = pl0 + 4 * jj;
            tile[pl][b] = g_ot[(size_t)(p0 + pl) * 8192 + (o << 6) + b];
        }
    }
    __syncthreads();
    {
        const int pl = tid & 31;
        const int b0 = tid >> 5;
        #pragma unroll
        for (int jj = 0; jj < 8; ++jj) {
            int b = b0 + 8 * jj;
            out[(((b << 7) + o) << 10) + p0 + pl] = tile[pl][b] + bss[pl];
        }
    }
}

extern "C" __global__ void __launch_bounds__(256, 3)
local2d_mma(const float* __restrict__ wgt)
{
    extern __shared__ char smem[];
    int*   offs    = reinterpret_cast<int*>(smem + SM_OFFS_B);
    float* stage0f = reinterpret_cast<float*>(smem + SM_STAGE_B);

    const int p    = blockIdx.x;
    const int h    = p >> 5;
    const int w    = p & 31;
    const int tid  = threadIdx.x;
    const int wid  = tid >> 5;
    const int lane = tid & 31;
    const int qr   = lane >> 2;
    const int qc   = lane & 3;

    // 8 warps: 4(o) x 2(b) grid of 32x32 warp tiles (bytes-optimal)
    const int wo  = wid & 3;
    const int wb  = wid >> 2;
    const int o0w = wo * 32;
    const int n0w = wb * 32;

    // async-copy mappings (256 threads)
    const int gor = tid >> 3;         // W: o row (j adds 32), 0..31
    const int gkq = tid & 7;          // W: float4 within KC

    const uint32_t sbase    = smem_u32(smem);
    const uint32_t stage_u0 = sbase + SM_STAGE_B;

    for (int k = tid; k < 576; k += 256) {
        int i  = k / 9;
        int r  = k - i * 9;
        int kk = r / 3;
        int ll = r - kk * 3;
        int y  = h - 1 + kk;
        int xw = w - 1 + ll;
        bool valid = ((unsigned)y < 32u) && ((unsigned)xw < 32u);
        offs[k] = valid ? ((((i << 5) + y) << 5) + xw) << 6 : -1;
    }
    __syncthreads();

    // issue cp.async copies for chunk cc into stage s
    #define ISSUE_CHUNK(cc, s) do {                                                \
        uint32_t Wb = stage_u0 + (uint32_t)(s) * (STAGE_F * 4);                    \
        uint32_t Pb = Wb + W_STAGE_F * 4;                                          \
        _Pragma("unroll")                                                          \
        for (int j = 0; j < 4; ++j) {                                              \
            int o = gor + 32 * j;                                                  \
            cp16(Wb + (uint32_t)(o * APITCH + gkq * 4) * 4,                        \
                 wgt + (o * 1024 + p) * 576 + (cc) * KC + gkq * 4, 16);            \
        }                                                                          \
        _Pragma("unroll")                                                          \
        for (int j = 0; j < 2; ++j) {                                              \
            int slot = tid + 256 * j;                                              \
            int kl   = slot >> 4;                                                  \
            int bq   = slot & 15;                                                  \
            int base = offs[(cc) * KC + kl];                                       \
            const float* src = g_xt + (base >= 0 ? base : 0) + bq * 4;             \
            cp16(Pb + (uint32_t)(kl * PPITCH + bq * 4) * 4, src,                   \
                 base >= 0 ? 16 : 0);                                              \
        }                                                                          \
        CP_COMMIT();                                                               \
    } while (0)

    float acc[2][4][4];
    #pragma unroll
    for (int mt = 0; mt < 2; ++mt)
        #pragma unroll
        for (int nt = 0; nt < 4; ++nt)
            #pragma unroll
            for (int e = 0; e < 4; ++e)
                acc[mt][nt][e] = 0.0f;

    ISSUE_CHUNK(0, 0);

    for (int c = 0; c < NCH; ++c) {
        const int s = c & 1;
        if (c + 1 < NCH) {
            ISSUE_CHUNK(c + 1, (c + 1) & 1);
            CP_WAIT(1);                 // chunk c complete, chunk c+1 in flight
        } else {
            CP_WAIT(0);
        }
        __syncthreads();

        const float* Ws = stage0f + s * STAGE_F;
        const float* Ps = Ws + W_STAGE_F;

        #pragma unroll
        for (int ks = 0; ks < 4; ++ks) {
            const int kb = ks * 8;
            uint32_t afr[2][4], bfr[4][2];
            #pragma unroll
            for (int mt = 0; mt < 2; ++mt) {
                const float* Ab = Ws + (o0w + mt * 16 + qr) * APITCH + kb + qc;
                afr[mt][0] = fbits(Ab[0]);
                afr[mt][1] = fbits(Ab[8 * APITCH]);
                afr[mt][2] = fbits(Ab[4]);
                afr[mt][3] = fbits(Ab[8 * APITCH + 4]);
            }
            #pragma unroll
            for (int nt = 0; nt < 4; ++nt) {
                const float* Bb = Ps + (kb + qc) * PPITCH + n0w + nt * 8 + qr;
                bfr[nt][0] = fbits(Bb[0]);
                bfr[nt][1] = fbits(Bb[4 * PPITCH]);
            }
            #pragma unroll
            for (int mt = 0; mt < 2; ++mt)
                #pragma unroll
                for (int nt = 0; nt < 4; ++nt)
                    mma_tf32(acc[mt][nt], afr[mt], bfr[nt]);
        }

        __syncthreads();   // all reads of stage s done before next issue overwrites it
    }

    // ---- epilogue: g_ot[p][o][b] = acc (contiguous per p, float2 stores) ----
    {
        float* op = g_ot + (size_t)p * 8192;
        #pragma unroll
        for (int mt = 0; mt < 2; ++mt) {
            const int ob = o0w + mt * 16 + qr;
            #pragma unroll
            for (int nt = 0; nt < 4; ++nt) {
                const int bb = n0w + nt * 8 + 2 * qc;
                *reinterpret_cast<float2*>(op + (ob << 6) + bb) =
                    make_float2(acc[mt][nt][0], acc[mt][nt][1]);
                *reinterpret_cast<float2*>(op + ((ob + 8) << 6) + bb) =
                    make_float2(acc[mt][nt][2], acc[mt][nt][3]);
            }
        }
    }
}

extern "C" void kernel_launch(void* const* d_in, const int* in_sizes, int n_in,
                              void* d_out, int out_size)
{
    const float* x    = (const float*)d_in[0];
    const float* wgt  = (const float*)d_in[1];
    const float* bias = (const float*)d_in[2];
    float* out        = (float*)d_out;

    xpose_kernel<<<2048, 256>>>(x);

    cudaFuncSetAttribute(local2d_mma,
                         cudaFuncAttributeMaxDynamicSharedMemorySize, SMEM_TOTAL);
    local2d_mma<<<1024, 256, SMEM_TOTAL>>>(wgt);

    opose_kernel<<<dim3(128, 32), 256>>>(bias, out);
}